// round 4
// baseline (speedup 1.0000x reference)
#include <cuda_runtime.h>
#include <cuda_bf16.h>
#include <cstdint>

// Problem shape (fixed by the dataset)
#define BB   32
#define TT   1000
#define VV   1024
#define LL   128
#define SS   (2*LL + 1)      // 257 extended lattice states
#define LPW  (LL + 1)        // 129 stored log-probs per (b,t): [blank, y1..yL]
#define NEGF (-1e30f)
#define L2E  1.4426950408889634f   // log2(e)
#define LN2  0.6931471805599453f   // ln(2)

// Scratch (no cudaMalloc allowed): log2-domain gathered log-probs + partials.
__device__ float g_lp2[(size_t)BB * TT * LPW];   // ~16.5 MB, L2-resident for DP
__device__ float g_part[BB];

// ---------------------------------------------------------------------------
// Kernel 1: per (b,t) log-sum-exp over V (base-2) + gather at blank/labels.
// One block per (b,t), 256 threads, 4 elements/thread.
// ---------------------------------------------------------------------------
__global__ __launch_bounds__(256) void k_lse_gather(
    const float* __restrict__ hs, const int* __restrict__ ys)
{
    const int bt  = blockIdx.x;            // = b*TT + t
    const int b   = bt / TT;
    const int tid = threadIdx.x;
    const int wid = tid >> 5, lane = tid & 31;

    const float* __restrict__ row = hs + (size_t)bt * VV;

    __shared__ float sh[VV];
    __shared__ float wred[8];
    __shared__ float bcast;

    // Load row (coalesced), convert to base-2 log domain, local max
    float v0 = row[tid          ] * L2E;
    float v1 = row[tid + 256    ] * L2E;
    float v2 = row[tid + 512    ] * L2E;
    float v3 = row[tid + 768    ] * L2E;
    sh[tid      ] = v0;
    sh[tid + 256] = v1;
    sh[tid + 512] = v2;
    sh[tid + 768] = v3;

    float m = fmaxf(fmaxf(v0, v1), fmaxf(v2, v3));
    #pragma unroll
    for (int o = 16; o > 0; o >>= 1)
        m = fmaxf(m, __shfl_xor_sync(0xffffffffu, m, o));
    if (lane == 0) wred[wid] = m;
    __syncthreads();
    if (tid == 0) {
        float mm = wred[0];
        #pragma unroll
        for (int i = 1; i < 8; i++) mm = fmaxf(mm, wred[i]);
        bcast = mm;
    }
    __syncthreads();
    m = bcast;

    // sum of exp2
    float s = exp2f(v0 - m) + exp2f(v1 - m) + exp2f(v2 - m) + exp2f(v3 - m);
    #pragma unroll
    for (int o = 16; o > 0; o >>= 1)
        s += __shfl_xor_sync(0xffffffffu, s, o);
    if (lane == 0) wred[wid] = s;
    __syncthreads();
    if (tid == 0) {
        float ss = wred[0];
        #pragma unroll
        for (int i = 1; i < 8; i++) ss += wred[i];
        bcast = m + log2f(ss);           // lse2 = log2(sum_j exp(x_j))
    }
    __syncthreads();
    const float lse2 = bcast;

    // Gather: slot 0 = blank(vocab 0), slots 1..128 = labels y1..yL
    if (tid < LPW) {
        int idx = (tid == 0) ? 0 : ys[b * LL + (tid - 1)];
        g_lp2[(size_t)bt * LPW + tid] = sh[idx] - lse2;
    }
}

// ---------------------------------------------------------------------------
// Kernel 2: CTC forward DP in log2 domain. One block per batch element.
// 288 threads (9 warps); thread s handles lattice state s (s < 257).
// Double-buffered shared alpha -> ONE barrier per time step; next step's
// lp is prefetched before the barrier so the L2 hit overlaps compute.
// ---------------------------------------------------------------------------
__global__ __launch_bounds__(288) void k_ctc_dp(
    const int* __restrict__ hlens, const int* __restrict__ ys,
    const int* __restrict__ ylens)
{
    const int b   = blockIdx.x;
    const int tid = threadIdx.x;
    const int s   = tid;
    const bool act = (s < SS);

    __shared__ float buf[2][SS + 2];     // [0],[1] = NEG padding for s-1, s-2

    const float* __restrict__ base = g_lp2 + (size_t)b * TT * LPW;

    // init both buffers (padding + alpha = NEG)
    for (int i = tid; i < 2 * (SS + 2); i += blockDim.x)
        (&buf[0][0])[i] = NEGF;
    __syncthreads();

    // per-thread constants
    int  off  = 0;
    bool skip = false;
    if (act) {
        off = (s & 1) ? (1 + (s >> 1)) : 0;     // lp slot for this state
        if ((s & 1) && s >= 3) {
            int k = (s - 1) >> 1;               // label index of state s
            skip = (ys[b * LL + k] != ys[b * LL + k - 1]);
        }
    }
    const int hlen = hlens[b];

    // alpha at t=0
    if (s == 0) buf[0][2 + 0] = base[0];
    if (s == 1) buf[0][2 + 1] = base[1];

    // prefetch lp for t=1
    float lpv = act ? base[(size_t)1 * LPW + off] : 0.0f;
    __syncthreads();

    int p = 0;
    for (int t = 1; t < TT; t++) {
        // issue next step's load early (hidden behind compute + barrier)
        float lpn = 0.0f;
        if (act & (t + 1 < TT)) lpn = base[(size_t)(t + 1) * LPW + off];

        if (act) {
            float a1 = buf[p][2 + s];
            float a2 = buf[p][1 + s];
            float m  = fmaxf(a1, a2);
            float e;
            if (skip) {
                float a3 = buf[p][s];
                float mm = fmaxf(m, a3);
                e = exp2f(a1 - mm) + exp2f(a2 - mm) + exp2f(a3 - mm);
                m = mm;
            } else {
                e = exp2f(a1 - m) + exp2f(a2 - m);
            }
            float nv = m + log2f(e) + lpv;
            if (t >= hlen) nv = a1;              // freeze past h_len
            buf[p ^ 1][2 + s] = nv;
        }
        __syncthreads();
        p ^= 1;
        lpv = lpn;
    }

    if (tid == 0) {
        const int yl = ylens[b];
        float ae1 = buf[p][2 + 2 * yl];
        float ae2 = buf[p][2 + 2 * yl - 1];
        float m   = fmaxf(ae1, ae2);
        float la2 = m + log2f(exp2f(ae1 - m) + exp2f(ae2 - m));
        g_part[b] = -(la2 * LN2) / (float)yl;    // back to natural log
    }
}

// ---------------------------------------------------------------------------
// Kernel 3: mean over batch.
// ---------------------------------------------------------------------------
__global__ void k_finish(float* __restrict__ out)
{
    int tid = threadIdx.x;
    float v = (tid < BB) ? g_part[tid] : 0.0f;
    #pragma unroll
    for (int o = 16; o > 0; o >>= 1)
        v += __shfl_xor_sync(0xffffffffu, v, o);
    if (tid == 0) out[0] = v / (float)BB;
}

extern "C" void kernel_launch(void* const* d_in, const int* in_sizes, int n_in,
                              void* d_out, int out_size)
{
    (void)in_sizes; (void)n_in; (void)out_size;
    const float* hs    = (const float*)d_in[0];
    const int*   hlens = (const int*)  d_in[1];
    const int*   ys    = (const int*)  d_in[2];
    const int*   ylens = (const int*)  d_in[3];
    float*       out   = (float*)d_out;

    k_lse_gather<<<BB * TT, 256>>>(hs, ys);
    k_ctc_dp<<<BB, 288>>>(hlens, ys, ylens);
    k_finish<<<1, 32>>>(out);
}